// round 1
// baseline (speedup 1.0000x reference)
#include <cuda_runtime.h>
#include <cuda_bf16.h>
#include <math.h>

// Problem constants (from reference)
#define NN_MAX 50000
#define C1TOT 128   // H1*C1 = 4*32
#define C2TOT 128

// ---------------- scratch (device globals; no allocation) ----------------
__device__ float    g_xw1 [NN_MAX * 128];   // xw of current layer
__device__ float    g_msg1[NN_MAX * 128];   // msg accum, then x2 in-place, then msg2
__device__ float    g_as1 [NN_MAX * 4];
__device__ float    g_ad1 [NN_MAX * 4];
__device__ float    g_den1[NN_MAX * 4];
__device__ unsigned g_m1u [NN_MAX * 4];
__device__ float    g_as2 [NN_MAX];
__device__ float    g_ad2 [NN_MAX];
__device__ float    g_den2[NN_MAX];
__device__ unsigned g_m2u [NN_MAX];
__device__ float    g_logits[NN_MAX];
__device__ unsigned g_maxu[1];
__device__ float    g_sum [1];

// ---------------- helpers ----------------
__device__ __forceinline__ unsigned ford(float f) {
    unsigned u = __float_as_uint(f);
    return (u & 0x80000000u) ? ~u : (u | 0x80000000u);
}
__device__ __forceinline__ float forddec(unsigned u) {
    return (u & 0x80000000u) ? __uint_as_float(u & 0x7fffffffu) : __uint_as_float(~u);
}
__device__ __forceinline__ float lrelu(float v) { return v > 0.f ? v : 0.2f * v; }
__device__ __forceinline__ float elu(float v)   { return v > 0.f ? v : expm1f(v); }

// ---------------- SGEMM: C[M,128] = A[M,K] @ B[K,128] ----------------
__global__ void sgemm128(const float* __restrict__ A, const float* __restrict__ B,
                         float* __restrict__ C, int M, int K) {
    __shared__ float As[16][128];
    __shared__ float Bs[16][128];
    int tid = threadIdx.x;                 // 256
    int row0 = blockIdx.x * 128;
    int tx = tid & 15, ty = tid >> 4;      // 16x16
    float acc[8][8];
#pragma unroll
    for (int i = 0; i < 8; i++)
#pragma unroll
        for (int j = 0; j < 8; j++) acc[i][j] = 0.f;

    for (int k0 = 0; k0 < K; k0 += 16) {
#pragma unroll
        for (int i = 0; i < 2; i++) {
            int v = tid + i * 256;         // 0..511 float4 id
            int r  = v >> 2;               // A row within tile
            int c4 = (v & 3) * 4;          // A col within tile
            float4 a = make_float4(0.f, 0.f, 0.f, 0.f);
            if (row0 + r < M)
                a = *(const float4*)&A[(size_t)(row0 + r) * K + k0 + c4];
            As[c4 + 0][r] = a.x; As[c4 + 1][r] = a.y;
            As[c4 + 2][r] = a.z; As[c4 + 3][r] = a.w;
            int br  = v >> 5;              // B row within tile (0..15)
            int bc4 = (v & 31) * 4;        // B col (0..124)
            *(float4*)&Bs[br][bc4] = *(const float4*)&B[(size_t)(k0 + br) * 128 + bc4];
        }
        __syncthreads();
#pragma unroll
        for (int k = 0; k < 16; k++) {
            float a[8], b[8];
#pragma unroll
            for (int i = 0; i < 8; i++) a[i] = As[k][ty * 8 + i];
#pragma unroll
            for (int j = 0; j < 8; j++) b[j] = Bs[k][tx * 8 + j];
#pragma unroll
            for (int i = 0; i < 8; i++)
#pragma unroll
                for (int j = 0; j < 8; j++) acc[i][j] += a[i] * b[j];
        }
        __syncthreads();
    }
#pragma unroll
    for (int i = 0; i < 8; i++) {
        int r = row0 + ty * 8 + i;
        if (r < M) {
#pragma unroll
            for (int j = 0; j < 8; j += 4) {
                float4 o = make_float4(acc[i][j], acc[i][j + 1], acc[i][j + 2], acc[i][j + 3]);
                *(float4*)&C[(size_t)r * 128 + tx * 8 + j] = o;
            }
        }
    }
}

// ---------------- layer-1 attention dots: [N,4] each ----------------
__global__ void attdot1(const float* __restrict__ asrc, const float* __restrict__ adst, int n) {
    int idx = blockIdx.x * blockDim.x + threadIdx.x;
    if (idx >= n * 4) return;
    int nn = idx >> 2, h = idx & 3;
    const float4* xr = (const float4*)&g_xw1[nn * 128 + h * 32];
    const float4* sr = (const float4*)&asrc[h * 32];
    const float4* dr = (const float4*)&adst[h * 32];
    float s = 0.f, d = 0.f;
#pragma unroll
    for (int i = 0; i < 8; i++) {
        float4 x = xr[i], aS = sr[i], aD = dr[i];
        s += x.x * aS.x + x.y * aS.y + x.z * aS.z + x.w * aS.w;
        d += x.x * aD.x + x.y * aD.y + x.z * aD.z + x.w * aD.w;
    }
    g_as1[idx] = s;
    g_ad1[idx] = d;
}

// ---------------- layer-1 segment max ----------------
__global__ void edge_max1(const int* __restrict__ src, const int* __restrict__ dst, int E, int n) {
    int e = blockIdx.x * blockDim.x + threadIdx.x;
    if (e >= E + n) return;
    int s, d;
    if (e < E) { s = src[e]; d = dst[e]; } else { s = e - E; d = s; }
    float4 as = *(const float4*)&g_as1[s * 4];
    float4 ad = *(const float4*)&g_ad1[d * 4];
    atomicMax(&g_m1u[d * 4 + 0], ford(lrelu(as.x + ad.x)));
    atomicMax(&g_m1u[d * 4 + 1], ford(lrelu(as.y + ad.y)));
    atomicMax(&g_m1u[d * 4 + 2], ford(lrelu(as.z + ad.z)));
    atomicMax(&g_m1u[d * 4 + 3], ford(lrelu(as.w + ad.w)));
}

// ---------------- layer-1 weighted scatter (warp per edge) ----------------
__global__ void edge_accum1(const int* __restrict__ src, const int* __restrict__ dst, int E, int n) {
    int w = (blockIdx.x * blockDim.x + threadIdx.x) >> 5;
    int lane = threadIdx.x & 31;
    if (w >= E + n) return;
    int s, d;
    if (w < E) { s = src[w]; d = dst[w]; } else { s = w - E; d = s; }
    int h = lane >> 3;
    float a = lrelu(g_as1[s * 4 + h] + g_ad1[d * 4 + h]);
    float m = forddec(g_m1u[d * 4 + h]);
    float wt = __expf(a - m);
    if ((lane & 7) == 0) atomicAdd(&g_den1[d * 4 + h], wt);
    float4 x = *(const float4*)&g_xw1[s * 128 + lane * 4];
    float* mp = &g_msg1[d * 128 + lane * 4];
    atomicAdd(mp + 0, wt * x.x);
    atomicAdd(mp + 1, wt * x.y);
    atomicAdd(mp + 2, wt * x.z);
    atomicAdd(mp + 3, wt * x.w);
}

// ---------------- layer-1 finish: x2 = elu(msg/den + b1) in place ----------------
__global__ void node_finish1(const float* __restrict__ b1, int n) {
    int idx = blockIdx.x * blockDim.x + threadIdx.x;
    if (idx >= n * 32) return;
    int nn = idx >> 5;
    int c4 = (idx & 31) * 4;
    int h = c4 >> 5;
    float inv = 1.f / (g_den1[nn * 4 + h] + 1e-16f);
    float4 m = *(float4*)&g_msg1[nn * 128 + c4];
    float4 b = *(const float4*)&b1[c4];
    m.x = elu(m.x * inv + b.x);
    m.y = elu(m.y * inv + b.y);
    m.z = elu(m.z * inv + b.z);
    m.w = elu(m.w * inv + b.w);
    *(float4*)&g_msg1[nn * 128 + c4] = m;
}

// ---------------- layer-2 attention dots (warp per node) ----------------
__global__ void attdot2(const float* __restrict__ asrc, const float* __restrict__ adst, int n) {
    int wn = (blockIdx.x * blockDim.x + threadIdx.x) >> 5;
    int lane = threadIdx.x & 31;
    if (wn >= n) return;
    float4 x  = *(const float4*)&g_xw1[wn * 128 + lane * 4];
    float4 aS = *(const float4*)&asrc[lane * 4];
    float4 aD = *(const float4*)&adst[lane * 4];
    float s = x.x * aS.x + x.y * aS.y + x.z * aS.z + x.w * aS.w;
    float d = x.x * aD.x + x.y * aD.y + x.z * aD.z + x.w * aD.w;
#pragma unroll
    for (int o = 16; o; o >>= 1) {
        s += __shfl_xor_sync(0xffffffffu, s, o);
        d += __shfl_xor_sync(0xffffffffu, d, o);
    }
    if (lane == 0) { g_as2[wn] = s; g_ad2[wn] = d; }
}

__global__ void edge_max2(const int* __restrict__ src, const int* __restrict__ dst, int E, int n) {
    int e = blockIdx.x * blockDim.x + threadIdx.x;
    if (e >= E + n) return;
    int s, d;
    if (e < E) { s = src[e]; d = dst[e]; } else { s = e - E; d = s; }
    atomicMax(&g_m2u[d], ford(lrelu(g_as2[s] + g_ad2[d])));
}

__global__ void edge_accum2(const int* __restrict__ src, const int* __restrict__ dst, int E, int n) {
    int w = (blockIdx.x * blockDim.x + threadIdx.x) >> 5;
    int lane = threadIdx.x & 31;
    if (w >= E + n) return;
    int s, d;
    if (w < E) { s = src[w]; d = dst[w]; } else { s = w - E; d = s; }
    float a = lrelu(g_as2[s] + g_ad2[d]);
    float wt = __expf(a - forddec(g_m2u[d]));
    if (lane == 0) atomicAdd(&g_den2[d], wt);
    float4 x = *(const float4*)&g_xw1[s * 128 + lane * 4];
    float* mp = &g_msg1[d * 128 + lane * 4];
    atomicAdd(mp + 0, wt * x.x);
    atomicAdd(mp + 1, wt * x.y);
    atomicAdd(mp + 2, wt * x.z);
    atomicAdd(mp + 3, wt * x.w);
}

// ---------------- layer-2 finish: ents + logits (warp per node) ----------------
__global__ void node_finish2(const float* __restrict__ b2, const float* __restrict__ Wq,
                             const int* __restrict__ qmask, float* __restrict__ ents, int n) {
    int wn = (blockIdx.x * blockDim.x + threadIdx.x) >> 5;
    int lane = threadIdx.x & 31;
    if (wn >= n) return;
    float inv = 1.f / (g_den2[wn] + 1e-16f);
    float4 m = *(const float4*)&g_msg1[wn * 128 + lane * 4];
    float4 b = *(const float4*)&b2[lane * 4];
    float4 v;
    v.x = elu(m.x * inv + b.x);
    v.y = elu(m.y * inv + b.y);
    v.z = elu(m.z * inv + b.z);
    v.w = elu(m.w * inv + b.w);
    *(float4*)&ents[(size_t)wn * 128 + lane * 4] = v;
    float4 wq = *(const float4*)&Wq[lane * 4];   // Wq[:128, 0]
    float dotp = v.x * wq.x + v.y * wq.y + v.z * wq.z + v.w * wq.w;
#pragma unroll
    for (int o = 16; o; o >>= 1) dotp += __shfl_xor_sync(0xffffffffu, dotp, o);
    if (lane == 0)
        g_logits[wn] = dotp + ((float)qmask[wn] - 1.f) * 1e9f;
}

// ---------------- softmax + pooling ----------------
__global__ void k_max(int n) {
    float m = -3.4e38f;
    for (int i = blockIdx.x * blockDim.x + threadIdx.x; i < n; i += gridDim.x * blockDim.x)
        m = fmaxf(m, g_logits[i]);
#pragma unroll
    for (int o = 16; o; o >>= 1) m = fmaxf(m, __shfl_xor_sync(0xffffffffu, m, o));
    if ((threadIdx.x & 31) == 0) atomicMax(&g_maxu[0], ford(m));
}

__global__ void k_expsum(float* __restrict__ e_out, int n) {
    float M = forddec(g_maxu[0]);
    float s = 0.f;
    for (int i = blockIdx.x * blockDim.x + threadIdx.x; i < n; i += gridDim.x * blockDim.x) {
        float e = __expf(g_logits[i] - M);
        e_out[i] = e;
        s += e;
    }
#pragma unroll
    for (int o = 16; o; o >>= 1) s += __shfl_xor_sync(0xffffffffu, s, o);
    if ((threadIdx.x & 31) == 0) atomicAdd(&g_sum[0], s);
}

__global__ void k_pool(const float* __restrict__ e, const float* __restrict__ ents,
                       float* __restrict__ pooled, int n) {
    int t = threadIdx.x;  // 128 = channel
    float acc = 0.f;
    for (int nn = blockIdx.x; nn < n; nn += gridDim.x)
        acc += e[nn] * ents[(size_t)nn * 128 + t];
    atomicAdd(&pooled[t], acc);
}

__global__ void k_norm(float* __restrict__ attn, float* __restrict__ pooled, int n) {
    float inv = 1.f / g_sum[0];
    for (int i = blockIdx.x * blockDim.x + threadIdx.x; i < n; i += gridDim.x * blockDim.x) {
        attn[i] *= inv;
        if (i < 128) pooled[i] *= inv;
    }
}

// ---------------- launch ----------------
extern "C" void kernel_launch(void* const* d_in, const int* in_sizes, int n_in,
                              void* d_out, int out_size) {
    const float* x     = (const float*)d_in[0];   // [N, F_IN]
    const int*   eidx  = (const int*)  d_in[1];   // [2, E]
    const int*   qmask = (const int*)  d_in[3];   // [N]
    const float* W1    = (const float*)d_in[5];
    const float* as1w  = (const float*)d_in[6];
    const float* ad1w  = (const float*)d_in[7];
    const float* b1    = (const float*)d_in[8];
    const float* W2    = (const float*)d_in[9];
    const float* as2w  = (const float*)d_in[10];
    const float* ad2w  = (const float*)d_in[11];
    const float* b2    = (const float*)d_in[12];
    const float* Wq    = (const float*)d_in[13];

    const int n = in_sizes[3];            // 50000
    const int E = in_sizes[1] / 2;        // 800000
    const int K1 = in_sizes[0] / n;       // 256
    const int ET = E + n;

    const int* src = eidx;
    const int* dst = eidx + E;

    float* out    = (float*)d_out;
    float* pooled = out;                   // [128]
    float* ents   = out + 128;             // [N,128]
    float* attn   = out + 128 + (size_t)n * 128;  // [N]

    // zero scratch
    void *p_m1u, *p_den1, *p_msg1, *p_m2u, *p_den2, *p_maxu, *p_sum;
    cudaGetSymbolAddress(&p_m1u,  g_m1u);
    cudaGetSymbolAddress(&p_den1, g_den1);
    cudaGetSymbolAddress(&p_msg1, g_msg1);
    cudaGetSymbolAddress(&p_m2u,  g_m2u);
    cudaGetSymbolAddress(&p_den2, g_den2);
    cudaGetSymbolAddress(&p_maxu, g_maxu);
    cudaGetSymbolAddress(&p_sum,  g_sum);

    cudaMemsetAsync(p_m1u,  0, (size_t)n * 4 * sizeof(unsigned));
    cudaMemsetAsync(p_den1, 0, (size_t)n * 4 * sizeof(float));
    cudaMemsetAsync(p_msg1, 0, (size_t)n * 128 * sizeof(float));
    cudaMemsetAsync(p_m2u,  0, (size_t)n * sizeof(unsigned));
    cudaMemsetAsync(p_den2, 0, (size_t)n * sizeof(float));
    cudaMemsetAsync(p_maxu, 0, sizeof(unsigned));
    cudaMemsetAsync(p_sum,  0, sizeof(float));
    cudaMemsetAsync(pooled, 0, 128 * sizeof(float));

    float* g_xw1_p;  cudaGetSymbolAddress((void**)&g_xw1_p,  g_xw1);
    float* g_msg1_p; cudaGetSymbolAddress((void**)&g_msg1_p, g_msg1);

    // ---- layer 1 ----
    sgemm128<<<(n + 127) / 128, 256>>>(x, W1, g_xw1_p, n, K1);
    attdot1<<<(n * 4 + 255) / 256, 256>>>(as1w, ad1w, n);
    edge_max1<<<(ET + 255) / 256, 256>>>(src, dst, E, n);
    edge_accum1<<<(ET + 7) / 8, 256>>>(src, dst, E, n);
    node_finish1<<<(n * 32 + 255) / 256, 256>>>(b1, n);

    // ---- layer 2 ----
    sgemm128<<<(n + 127) / 128, 256>>>(g_msg1_p, W2, g_xw1_p, n, 128);
    attdot2<<<(n + 7) / 8, 256>>>(as2w, ad2w, n);
    cudaMemsetAsync(p_msg1, 0, (size_t)n * 128 * sizeof(float));
    edge_max2<<<(ET + 255) / 256, 256>>>(src, dst, E, n);
    edge_accum2<<<(ET + 7) / 8, 256>>>(src, dst, E, n);
    node_finish2<<<(n + 7) / 8, 256>>>(b2, Wq, qmask, ents, n);

    // ---- softmax + pool ----
    k_max<<<256, 256>>>(n);
    k_expsum<<<256, 256>>>(attn, n);
    k_pool<<<512, 128>>>(attn, ents, pooled, n);
    k_norm<<<(n + 255) / 256, 256>>>(attn, pooled, n);
}

// round 2
// speedup vs baseline: 1.5548x; 1.5548x over previous
#include <cuda_runtime.h>
#include <cuda_bf16.h>
#include <math.h>

#define NN_MAX 50000

// ---------------- scratch (device globals; no allocation) ----------------
__device__ float    g_xw1 [NN_MAX * 128];
__device__ float    g_msg1[NN_MAX * 128];
__device__ float    g_as1 [NN_MAX * 4];
__device__ float    g_ad1 [NN_MAX * 4];
__device__ float    g_den1[NN_MAX * 4];
__device__ unsigned g_m1u [NN_MAX * 4];
__device__ float    g_as2 [NN_MAX];
__device__ float    g_ad2 [NN_MAX];
__device__ float    g_den2[NN_MAX];
__device__ unsigned g_m2u [NN_MAX];
__device__ float    g_logits[NN_MAX];
__device__ unsigned g_maxu[1];
__device__ float    g_sum [1];

// ---------------- helpers ----------------
__device__ __forceinline__ unsigned ford(float f) {
    unsigned u = __float_as_uint(f);
    return (u & 0x80000000u) ? ~u : (u | 0x80000000u);
}
__device__ __forceinline__ float forddec(unsigned u) {
    return (u & 0x80000000u) ? __uint_as_float(u & 0x7fffffffu) : __uint_as_float(~u);
}
__device__ __forceinline__ float lrelu(float v) { return v > 0.f ? v : 0.2f * v; }
__device__ __forceinline__ float elu(float v)   { return v > 0.f ? v : expm1f(v); }

// 128-bit no-return global float add (sm_90+): 1 instr instead of 4 scalar atomics
__device__ __forceinline__ void red_add_v4(float* addr, float x, float y, float z, float w) {
    asm volatile("red.global.add.v4.f32 [%0], {%1, %2, %3, %4};"
                 :: "l"(addr), "f"(x), "f"(y), "f"(z), "f"(w) : "memory");
}

// ---------------- SGEMM: C[M,128] = A[M,K] @ B[K,128] ----------------
__global__ void sgemm128(const float* __restrict__ A, const float* __restrict__ B,
                         float* __restrict__ C, int M, int K) {
    __shared__ float As[16][128];
    __shared__ float Bs[16][128];
    int tid = threadIdx.x;                 // 256
    int row0 = blockIdx.x * 128;
    int tx = tid & 15, ty = tid >> 4;      // 16x16
    float acc[8][8];
#pragma unroll
    for (int i = 0; i < 8; i++)
#pragma unroll
        for (int j = 0; j < 8; j++) acc[i][j] = 0.f;

    for (int k0 = 0; k0 < K; k0 += 16) {
#pragma unroll
        for (int i = 0; i < 2; i++) {
            int v = tid + i * 256;
            int r  = v >> 2;
            int c4 = (v & 3) * 4;
            float4 a = make_float4(0.f, 0.f, 0.f, 0.f);
            if (row0 + r < M)
                a = *(const float4*)&A[(size_t)(row0 + r) * K + k0 + c4];
            As[c4 + 0][r] = a.x; As[c4 + 1][r] = a.y;
            As[c4 + 2][r] = a.z; As[c4 + 3][r] = a.w;
            int br  = v >> 5;
            int bc4 = (v & 31) * 4;
            *(float4*)&Bs[br][bc4] = *(const float4*)&B[(size_t)(k0 + br) * 128 + bc4];
        }
        __syncthreads();
#pragma unroll
        for (int k = 0; k < 16; k++) {
            float a[8], b[8];
#pragma unroll
            for (int i = 0; i < 8; i++) a[i] = As[k][ty * 8 + i];
#pragma unroll
            for (int j = 0; j < 8; j++) b[j] = Bs[k][tx * 8 + j];
#pragma unroll
            for (int i = 0; i < 8; i++)
#pragma unroll
                for (int j = 0; j < 8; j++) acc[i][j] += a[i] * b[j];
        }
        __syncthreads();
    }
#pragma unroll
    for (int i = 0; i < 8; i++) {
        int r = row0 + ty * 8 + i;
        if (r < M) {
#pragma unroll
            for (int j = 0; j < 8; j += 4) {
                float4 o = make_float4(acc[i][j], acc[i][j + 1], acc[i][j + 2], acc[i][j + 3]);
                *(float4*)&C[(size_t)r * 128 + tx * 8 + j] = o;
            }
        }
    }
}

// ---------------- layer-1 attention dots ----------------
__global__ void attdot1(const float* __restrict__ asrc, const float* __restrict__ adst, int n) {
    int idx = blockIdx.x * blockDim.x + threadIdx.x;
    if (idx >= n * 4) return;
    int nn = idx >> 2, h = idx & 3;
    const float4* xr = (const float4*)&g_xw1[nn * 128 + h * 32];
    const float4* sr = (const float4*)&asrc[h * 32];
    const float4* dr = (const float4*)&adst[h * 32];
    float s = 0.f, d = 0.f;
#pragma unroll
    for (int i = 0; i < 8; i++) {
        float4 x = xr[i], aS = sr[i], aD = dr[i];
        s += x.x * aS.x + x.y * aS.y + x.z * aS.z + x.w * aS.w;
        d += x.x * aD.x + x.y * aD.y + x.z * aD.z + x.w * aD.w;
    }
    g_as1[idx] = s;
    g_ad1[idx] = d;
}

// ---------------- layer-1 segment max ----------------
__global__ void edge_max1(const int* __restrict__ src, const int* __restrict__ dst, int E, int n) {
    int e = blockIdx.x * blockDim.x + threadIdx.x;
    if (e >= E + n) return;
    int s, d;
    if (e < E) { s = src[e]; d = dst[e]; } else { s = e - E; d = s; }
    float4 as = *(const float4*)&g_as1[s * 4];
    float4 ad = *(const float4*)&g_ad1[d * 4];
    atomicMax(&g_m1u[d * 4 + 0], ford(lrelu(as.x + ad.x)));
    atomicMax(&g_m1u[d * 4 + 1], ford(lrelu(as.y + ad.y)));
    atomicMax(&g_m1u[d * 4 + 2], ford(lrelu(as.z + ad.z)));
    atomicMax(&g_m1u[d * 4 + 3], ford(lrelu(as.w + ad.w)));
}

// ---------------- layer-1 weighted scatter (warp per edge, v4 red) ----------------
__global__ void edge_accum1(const int* __restrict__ src, const int* __restrict__ dst, int E, int n) {
    int w = (blockIdx.x * blockDim.x + threadIdx.x) >> 5;
    int lane = threadIdx.x & 31;
    if (w >= E + n) return;
    int s, d;
    if (w < E) { s = src[w]; d = dst[w]; } else { s = w - E; d = s; }
    int h = lane >> 3;
    float a = lrelu(g_as1[s * 4 + h] + g_ad1[d * 4 + h]);
    float m = forddec(g_m1u[d * 4 + h]);
    float wt = __expf(a - m);
    if ((lane & 7) == 0) atomicAdd(&g_den1[d * 4 + h], wt);
    float4 x = *(const float4*)&g_xw1[s * 128 + lane * 4];
    red_add_v4(&g_msg1[d * 128 + lane * 4], wt * x.x, wt * x.y, wt * x.z, wt * x.w);
}

// ---------------- layer-1 finish ----------------
__global__ void node_finish1(const float* __restrict__ b1, int n) {
    int idx = blockIdx.x * blockDim.x + threadIdx.x;
    if (idx >= n * 32) return;
    int nn = idx >> 5;
    int c4 = (idx & 31) * 4;
    int h = c4 >> 5;
    float inv = 1.f / (g_den1[nn * 4 + h] + 1e-16f);
    float4 m = *(float4*)&g_msg1[nn * 128 + c4];
    float4 b = *(const float4*)&b1[c4];
    m.x = elu(m.x * inv + b.x);
    m.y = elu(m.y * inv + b.y);
    m.z = elu(m.z * inv + b.z);
    m.w = elu(m.w * inv + b.w);
    *(float4*)&g_msg1[nn * 128 + c4] = m;
}

// ---------------- layer-2 attention dots (warp per node) ----------------
__global__ void attdot2(const float* __restrict__ asrc, const float* __restrict__ adst, int n) {
    int wn = (blockIdx.x * blockDim.x + threadIdx.x) >> 5;
    int lane = threadIdx.x & 31;
    if (wn >= n) return;
    float4 x  = *(const float4*)&g_xw1[wn * 128 + lane * 4];
    float4 aS = *(const float4*)&asrc[lane * 4];
    float4 aD = *(const float4*)&adst[lane * 4];
    float s = x.x * aS.x + x.y * aS.y + x.z * aS.z + x.w * aS.w;
    float d = x.x * aD.x + x.y * aD.y + x.z * aD.z + x.w * aD.w;
#pragma unroll
    for (int o = 16; o; o >>= 1) {
        s += __shfl_xor_sync(0xffffffffu, s, o);
        d += __shfl_xor_sync(0xffffffffu, d, o);
    }
    if (lane == 0) { g_as2[wn] = s; g_ad2[wn] = d; }
}

__global__ void edge_max2(const int* __restrict__ src, const int* __restrict__ dst, int E, int n) {
    int e = blockIdx.x * blockDim.x + threadIdx.x;
    if (e >= E + n) return;
    int s, d;
    if (e < E) { s = src[e]; d = dst[e]; } else { s = e - E; d = s; }
    atomicMax(&g_m2u[d], ford(lrelu(g_as2[s] + g_ad2[d])));
}

__global__ void edge_accum2(const int* __restrict__ src, const int* __restrict__ dst, int E, int n) {
    int w = (blockIdx.x * blockDim.x + threadIdx.x) >> 5;
    int lane = threadIdx.x & 31;
    if (w >= E + n) return;
    int s, d;
    if (w < E) { s = src[w]; d = dst[w]; } else { s = w - E; d = s; }
    float a = lrelu(g_as2[s] + g_ad2[d]);
    float wt = __expf(a - forddec(g_m2u[d]));
    if (lane == 0) atomicAdd(&g_den2[d], wt);
    float4 x = *(const float4*)&g_xw1[s * 128 + lane * 4];
    red_add_v4(&g_msg1[d * 128 + lane * 4], wt * x.x, wt * x.y, wt * x.z, wt * x.w);
}

// ---------------- layer-2 finish: ents + logits (warp per node) ----------------
__global__ void node_finish2(const float* __restrict__ b2, const float* __restrict__ Wq,
                             const int* __restrict__ qmask, float* __restrict__ ents, int n) {
    int wn = (blockIdx.x * blockDim.x + threadIdx.x) >> 5;
    int lane = threadIdx.x & 31;
    if (wn >= n) return;
    float inv = 1.f / (g_den2[wn] + 1e-16f);
    float4 m = *(const float4*)&g_msg1[wn * 128 + lane * 4];
    float4 b = *(const float4*)&b2[lane * 4];
    float4 v;
    v.x = elu(m.x * inv + b.x);
    v.y = elu(m.y * inv + b.y);
    v.z = elu(m.z * inv + b.z);
    v.w = elu(m.w * inv + b.w);
    *(float4*)&ents[(size_t)wn * 128 + lane * 4] = v;
    float4 wq = *(const float4*)&Wq[lane * 4];
    float dotp = v.x * wq.x + v.y * wq.y + v.z * wq.z + v.w * wq.w;
#pragma unroll
    for (int o = 16; o; o >>= 1) dotp += __shfl_xor_sync(0xffffffffu, dotp, o);
    if (lane == 0)
        g_logits[wn] = dotp + ((float)qmask[wn] - 1.f) * 1e9f;
}

// ---------------- softmax + pooling ----------------
__global__ void k_max(int n) {
    float m = -3.4e38f;
    for (int i = blockIdx.x * blockDim.x + threadIdx.x; i < n; i += gridDim.x * blockDim.x)
        m = fmaxf(m, g_logits[i]);
#pragma unroll
    for (int o = 16; o; o >>= 1) m = fmaxf(m, __shfl_xor_sync(0xffffffffu, m, o));
    if ((threadIdx.x & 31) == 0) atomicMax(&g_maxu[0], ford(m));
}

__global__ void k_expsum(float* __restrict__ e_out, int n) {
    float M = forddec(g_maxu[0]);
    float s = 0.f;
    for (int i = blockIdx.x * blockDim.x + threadIdx.x; i < n; i += gridDim.x * blockDim.x) {
        float e = __expf(g_logits[i] - M);
        e_out[i] = e;
        s += e;
    }
#pragma unroll
    for (int o = 16; o; o >>= 1) s += __shfl_xor_sync(0xffffffffu, s, o);
    if ((threadIdx.x & 31) == 0) atomicAdd(&g_sum[0], s);
}

__global__ void k_pool(const float* __restrict__ e, const float* __restrict__ ents,
                       float* __restrict__ pooled, int n) {
    int t = threadIdx.x;  // 128 = channel
    float acc = 0.f;
    for (int nn = blockIdx.x; nn < n; nn += gridDim.x)
        acc += e[nn] * ents[(size_t)nn * 128 + t];
    atomicAdd(&pooled[t], acc);
}

__global__ void k_norm(float* __restrict__ attn, float* __restrict__ pooled, int n) {
    float inv = 1.f / g_sum[0];
    for (int i = blockIdx.x * blockDim.x + threadIdx.x; i < n; i += gridDim.x * blockDim.x) {
        attn[i] *= inv;
        if (i < 128) pooled[i] *= inv;
    }
}

// ---------------- launch ----------------
extern "C" void kernel_launch(void* const* d_in, const int* in_sizes, int n_in,
                              void* d_out, int out_size) {
    const float* x     = (const float*)d_in[0];
    const int*   eidx  = (const int*)  d_in[1];
    const int*   qmask = (const int*)  d_in[3];
    const float* W1    = (const float*)d_in[5];
    const float* as1w  = (const float*)d_in[6];
    const float* ad1w  = (const float*)d_in[7];
    const float* b1    = (const float*)d_in[8];
    const float* W2    = (const float*)d_in[9];
    const float* as2w  = (const float*)d_in[10];
    const float* ad2w  = (const float*)d_in[11];
    const float* b2    = (const float*)d_in[12];
    const float* Wq    = (const float*)d_in[13];

    const int n = in_sizes[3];
    const int E = in_sizes[1] / 2;
    const int K1 = in_sizes[0] / n;
    const int ET = E + n;

    const int* src = eidx;
    const int* dst = eidx + E;

    float* out    = (float*)d_out;
    float* pooled = out;
    float* ents   = out + 128;
    float* attn   = out + 128 + (size_t)n * 128;

    void *p_m1u, *p_den1, *p_msg1, *p_m2u, *p_den2, *p_maxu, *p_sum;
    cudaGetSymbolAddress(&p_m1u,  g_m1u);
    cudaGetSymbolAddress(&p_den1, g_den1);
    cudaGetSymbolAddress(&p_msg1, g_msg1);
    cudaGetSymbolAddress(&p_m2u,  g_m2u);
    cudaGetSymbolAddress(&p_den2, g_den2);
    cudaGetSymbolAddress(&p_maxu, g_maxu);
    cudaGetSymbolAddress(&p_sum,  g_sum);

    cudaMemsetAsync(p_m1u,  0, (size_t)n * 4 * sizeof(unsigned));
    cudaMemsetAsync(p_den1, 0, (size_t)n * 4 * sizeof(float));
    cudaMemsetAsync(p_msg1, 0, (size_t)n * 128 * sizeof(float));
    cudaMemsetAsync(p_m2u,  0, (size_t)n * sizeof(unsigned));
    cudaMemsetAsync(p_den2, 0, (size_t)n * sizeof(float));
    cudaMemsetAsync(p_maxu, 0, sizeof(unsigned));
    cudaMemsetAsync(p_sum,  0, sizeof(float));
    cudaMemsetAsync(pooled, 0, 128 * sizeof(float));

    float* g_xw1_p;  cudaGetSymbolAddress((void**)&g_xw1_p,  g_xw1);
    float* g_msg1_p; cudaGetSymbolAddress((void**)&g_msg1_p, g_msg1);

    // ---- layer 1 ----
    sgemm128<<<(n + 127) / 128, 256>>>(x, W1, g_xw1_p, n, K1);
    attdot1<<<(n * 4 + 255) / 256, 256>>>(as1w, ad1w, n);
    edge_max1<<<(ET + 255) / 256, 256>>>(src, dst, E, n);
    edge_accum1<<<(ET + 7) / 8, 256>>>(src, dst, E, n);
    node_finish1<<<(n * 32 + 255) / 256, 256>>>(b1, n);

    // ---- layer 2 ----
    sgemm128<<<(n + 127) / 128, 256>>>(g_msg1_p, W2, g_xw1_p, n, 128);
    attdot2<<<(n + 7) / 8, 256>>>(as2w, ad2w, n);
    cudaMemsetAsync(p_msg1, 0, (size_t)n * 128 * sizeof(float));
    edge_max2<<<(ET + 255) / 256, 256>>>(src, dst, E, n);
    edge_accum2<<<(ET + 7) / 8, 256>>>(src, dst, E, n);
    node_finish2<<<(n + 7) / 8, 256>>>(b2, Wq, qmask, ents, n);

    // ---- softmax + pool ----
    k_max<<<256, 256>>>(n);
    k_expsum<<<256, 256>>>(attn, n);
    k_pool<<<512, 128>>>(attn, ents, pooled, n);
    k_norm<<<(n + 255) / 256, 256>>>(attn, pooled, n);
}

// round 3
// speedup vs baseline: 1.9480x; 1.2529x over previous
#include <cuda_runtime.h>
#include <cuda_bf16.h>
#include <math.h>

#define NN_MAX 50000
#define E_MAX  800000

// ---------------- scratch (device globals; no allocation) ----------------
__device__ float    g_xw1 [NN_MAX * 128];
__device__ float    g_msg1[NN_MAX * 128];        // layer-1 output x2
__device__ float    g_as1 [NN_MAX * 4];
__device__ float    g_ad1 [NN_MAX * 4];
__device__ float    g_as2 [NN_MAX];
__device__ float    g_ad2 [NN_MAX];
__device__ float    g_logits[NN_MAX];
__device__ unsigned g_maxu[1];
__device__ float    g_sum [1];
// CSR
__device__ int      g_deg   [NN_MAX];
__device__ int      g_rowptr[NN_MAX + 1];
__device__ int      g_cursor[NN_MAX];
__device__ int      g_col   [E_MAX + NN_MAX];

// ---------------- helpers ----------------
__device__ __forceinline__ unsigned ford(float f) {
    unsigned u = __float_as_uint(f);
    return (u & 0x80000000u) ? ~u : (u | 0x80000000u);
}
__device__ __forceinline__ float forddec(unsigned u) {
    return (u & 0x80000000u) ? __uint_as_float(u & 0x7fffffffu) : __uint_as_float(~u);
}
__device__ __forceinline__ float lrelu(float v) { return v > 0.f ? v : 0.2f * v; }
__device__ __forceinline__ float elu(float v)   { return v > 0.f ? v : expm1f(v); }

// ---------------- SGEMM: C[M,128] = A[M,K] @ B[K,128] ----------------
__global__ void sgemm128(const float* __restrict__ A, const float* __restrict__ B,
                         float* __restrict__ C, int M, int K) {
    __shared__ float As[16][128];
    __shared__ float Bs[16][128];
    int tid = threadIdx.x;                 // 256
    int row0 = blockIdx.x * 128;
    int tx = tid & 15, ty = tid >> 4;      // 16x16
    float acc[8][8];
#pragma unroll
    for (int i = 0; i < 8; i++)
#pragma unroll
        for (int j = 0; j < 8; j++) acc[i][j] = 0.f;

    for (int k0 = 0; k0 < K; k0 += 16) {
#pragma unroll
        for (int i = 0; i < 2; i++) {
            int v = tid + i * 256;
            int r  = v >> 2;
            int c4 = (v & 3) * 4;
            float4 a = make_float4(0.f, 0.f, 0.f, 0.f);
            if (row0 + r < M)
                a = *(const float4*)&A[(size_t)(row0 + r) * K + k0 + c4];
            As[c4 + 0][r] = a.x; As[c4 + 1][r] = a.y;
            As[c4 + 2][r] = a.z; As[c4 + 3][r] = a.w;
            int br  = v >> 5;
            int bc4 = (v & 31) * 4;
            *(float4*)&Bs[br][bc4] = *(const float4*)&B[(size_t)(k0 + br) * 128 + bc4];
        }
        __syncthreads();
#pragma unroll
        for (int k = 0; k < 16; k++) {
            float a[8], b[8];
#pragma unroll
            for (int i = 0; i < 8; i++) a[i] = As[k][ty * 8 + i];
#pragma unroll
            for (int j = 0; j < 8; j++) b[j] = Bs[k][tx * 8 + j];
#pragma unroll
            for (int i = 0; i < 8; i++)
#pragma unroll
                for (int j = 0; j < 8; j++) acc[i][j] += a[i] * b[j];
        }
        __syncthreads();
    }
#pragma unroll
    for (int i = 0; i < 8; i++) {
        int r = row0 + ty * 8 + i;
        if (r < M) {
#pragma unroll
            for (int j = 0; j < 8; j += 4) {
                float4 o = make_float4(acc[i][j], acc[i][j + 1], acc[i][j + 2], acc[i][j + 3]);
                *(float4*)&C[(size_t)r * 128 + tx * 8 + j] = o;
            }
        }
    }
}

// ---------------- CSR build ----------------
__global__ void k_hist(const int* __restrict__ dst, int E, int n) {
    int e = blockIdx.x * blockDim.x + threadIdx.x;
    if (e >= E + n) return;
    int d = (e < E) ? dst[e] : (e - E);
    atomicAdd(&g_deg[d], 1);
}

__global__ void k_prefix(int n) {
    __shared__ int sh[1024];
    int t = threadIdx.x;
    int chunk = (n + 1023) / 1024;
    int lo = t * chunk, hi = min(lo + chunk, n);
    int part = 0;
    for (int i = lo; i < hi; i++) part += g_deg[i];
    sh[t] = part;
    __syncthreads();
    // inclusive scan
    for (int off = 1; off < 1024; off <<= 1) {
        int v = (t >= off) ? sh[t - off] : 0;
        __syncthreads();
        sh[t] += v;
        __syncthreads();
    }
    int base = (t == 0) ? 0 : sh[t - 1];
    for (int i = lo; i < hi; i++) {
        g_rowptr[i] = base;
        g_cursor[i] = base;
        base += g_deg[i];
    }
    if (t == 0) g_rowptr[n] = sh[1023];
}

__global__ void k_scatter(const int* __restrict__ src, const int* __restrict__ dst, int E, int n) {
    int e = blockIdx.x * blockDim.x + threadIdx.x;
    if (e >= E + n) return;
    int s, d;
    if (e < E) { s = src[e]; d = dst[e]; } else { s = e - E; d = s; }
    int pos = atomicAdd(&g_cursor[d], 1);
    g_col[pos] = s;
}

// ---------------- layer-1 attention dots ----------------
__global__ void attdot1(const float* __restrict__ asrc, const float* __restrict__ adst, int n) {
    int idx = blockIdx.x * blockDim.x + threadIdx.x;
    if (idx >= n * 4) return;
    int nn = idx >> 2, h = idx & 3;
    const float4* xr = (const float4*)&g_xw1[nn * 128 + h * 32];
    const float4* sr = (const float4*)&asrc[h * 32];
    const float4* dr = (const float4*)&adst[h * 32];
    float s = 0.f, d = 0.f;
#pragma unroll
    for (int i = 0; i < 8; i++) {
        float4 x = xr[i], aS = sr[i], aD = dr[i];
        s += x.x * aS.x + x.y * aS.y + x.z * aS.z + x.w * aS.w;
        d += x.x * aD.x + x.y * aD.y + x.z * aD.z + x.w * aD.w;
    }
    g_as1[idx] = s;
    g_ad1[idx] = d;
}

// ---------------- layer-1 gather: softmax-aggregate, fused finish ----------------
__global__ void gather1(const float* __restrict__ b1, int n) {
    int d = (blockIdx.x * blockDim.x + threadIdx.x) >> 5;
    int lane = threadIdx.x & 31;
    if (d >= n) return;
    int r0 = g_rowptr[d], r1 = g_rowptr[d + 1];
    float4 ad = *(const float4*)&g_ad1[d * 4];

    // max phase: lanes stride edges
    float4 mx = make_float4(-3.4e38f, -3.4e38f, -3.4e38f, -3.4e38f);
    for (int e = r0 + lane; e < r1; e += 32) {
        int s = g_col[e];
        float4 as = *(const float4*)&g_as1[s * 4];
        mx.x = fmaxf(mx.x, lrelu(as.x + ad.x));
        mx.y = fmaxf(mx.y, lrelu(as.y + ad.y));
        mx.z = fmaxf(mx.z, lrelu(as.z + ad.z));
        mx.w = fmaxf(mx.w, lrelu(as.w + ad.w));
    }
#pragma unroll
    for (int o = 16; o; o >>= 1) {
        mx.x = fmaxf(mx.x, __shfl_xor_sync(0xffffffffu, mx.x, o));
        mx.y = fmaxf(mx.y, __shfl_xor_sync(0xffffffffu, mx.y, o));
        mx.z = fmaxf(mx.z, __shfl_xor_sync(0xffffffffu, mx.z, o));
        mx.w = fmaxf(mx.w, __shfl_xor_sync(0xffffffffu, mx.w, o));
    }

    int h = lane >> 3;
    float m_h  = (h == 0) ? mx.x : (h == 1) ? mx.y : (h == 2) ? mx.z : mx.w;
    float ad_h = (h == 0) ? ad.x : (h == 1) ? ad.y : (h == 2) ? ad.z : ad.w;

    // accumulate phase: whole warp per edge; per-lane den is identical within octet
    float4 acc = make_float4(0.f, 0.f, 0.f, 0.f);
    float den = 0.f;
    for (int e = r0; e < r1; e++) {
        int s = g_col[e];
        float as_h = g_as1[s * 4 + h];
        float wt = __expf(lrelu(as_h + ad_h) - m_h);
        den += wt;
        float4 x = *(const float4*)&g_xw1[s * 128 + lane * 4];
        acc.x += wt * x.x; acc.y += wt * x.y;
        acc.z += wt * x.z; acc.w += wt * x.w;
    }
    float inv = 1.f / (den + 1e-16f);
    float4 b = *(const float4*)&b1[lane * 4];
    float4 v;
    v.x = elu(acc.x * inv + b.x);
    v.y = elu(acc.y * inv + b.y);
    v.z = elu(acc.z * inv + b.z);
    v.w = elu(acc.w * inv + b.w);
    *(float4*)&g_msg1[d * 128 + lane * 4] = v;
}

// ---------------- layer-2 attention dots (warp per node) ----------------
__global__ void attdot2(const float* __restrict__ asrc, const float* __restrict__ adst, int n) {
    int wn = (blockIdx.x * blockDim.x + threadIdx.x) >> 5;
    int lane = threadIdx.x & 31;
    if (wn >= n) return;
    float4 x  = *(const float4*)&g_xw1[wn * 128 + lane * 4];
    float4 aS = *(const float4*)&asrc[lane * 4];
    float4 aD = *(const float4*)&adst[lane * 4];
    float s = x.x * aS.x + x.y * aS.y + x.z * aS.z + x.w * aS.w;
    float d = x.x * aD.x + x.y * aD.y + x.z * aD.z + x.w * aD.w;
#pragma unroll
    for (int o = 16; o; o >>= 1) {
        s += __shfl_xor_sync(0xffffffffu, s, o);
        d += __shfl_xor_sync(0xffffffffu, d, o);
    }
    if (lane == 0) { g_as2[wn] = s; g_ad2[wn] = d; }
}

// ---------------- layer-2 gather: fused ents + logits ----------------
__global__ void gather2(const float* __restrict__ b2, const float* __restrict__ Wq,
                        const int* __restrict__ qmask, float* __restrict__ ents, int n) {
    int d = (blockIdx.x * blockDim.x + threadIdx.x) >> 5;
    int lane = threadIdx.x & 31;
    if (d >= n) return;
    int r0 = g_rowptr[d], r1 = g_rowptr[d + 1];
    float ad = g_ad2[d];

    float mx = -3.4e38f;
    for (int e = r0 + lane; e < r1; e += 32)
        mx = fmaxf(mx, lrelu(g_as2[g_col[e]] + ad));
#pragma unroll
    for (int o = 16; o; o >>= 1) mx = fmaxf(mx, __shfl_xor_sync(0xffffffffu, mx, o));

    float4 acc = make_float4(0.f, 0.f, 0.f, 0.f);
    float den = 0.f;
    for (int e = r0; e < r1; e++) {
        int s = g_col[e];
        float wt = __expf(lrelu(g_as2[s] + ad) - mx);
        den += wt;
        float4 x = *(const float4*)&g_xw1[s * 128 + lane * 4];
        acc.x += wt * x.x; acc.y += wt * x.y;
        acc.z += wt * x.z; acc.w += wt * x.w;
    }
    float inv = 1.f / (den + 1e-16f);
    float4 b = *(const float4*)&b2[lane * 4];
    float4 v;
    v.x = elu(acc.x * inv + b.x);
    v.y = elu(acc.y * inv + b.y);
    v.z = elu(acc.z * inv + b.z);
    v.w = elu(acc.w * inv + b.w);
    *(float4*)&ents[(size_t)d * 128 + lane * 4] = v;

    float4 wq = *(const float4*)&Wq[lane * 4];   // Wq[:128, 0]
    float dotp = v.x * wq.x + v.y * wq.y + v.z * wq.z + v.w * wq.w;
#pragma unroll
    for (int o = 16; o; o >>= 1) dotp += __shfl_xor_sync(0xffffffffu, dotp, o);
    if (lane == 0)
        g_logits[d] = dotp + ((float)qmask[d] - 1.f) * 1e9f;
}

// ---------------- softmax + pooling ----------------
__global__ void k_max(int n) {
    float m = -3.4e38f;
    for (int i = blockIdx.x * blockDim.x + threadIdx.x; i < n; i += gridDim.x * blockDim.x)
        m = fmaxf(m, g_logits[i]);
#pragma unroll
    for (int o = 16; o; o >>= 1) m = fmaxf(m, __shfl_xor_sync(0xffffffffu, m, o));
    if ((threadIdx.x & 31) == 0) atomicMax(&g_maxu[0], ford(m));
}

__global__ void k_expsum(float* __restrict__ e_out, int n) {
    float M = forddec(g_maxu[0]);
    float s = 0.f;
    for (int i = blockIdx.x * blockDim.x + threadIdx.x; i < n; i += gridDim.x * blockDim.x) {
        float e = __expf(g_logits[i] - M);
        e_out[i] = e;
        s += e;
    }
#pragma unroll
    for (int o = 16; o; o >>= 1) s += __shfl_xor_sync(0xffffffffu, s, o);
    if ((threadIdx.x & 31) == 0) atomicAdd(&g_sum[0], s);
}

__global__ void k_pool(const float* __restrict__ e, const float* __restrict__ ents,
                       float* __restrict__ pooled, int n) {
    int t = threadIdx.x;  // 128 = channel
    float acc = 0.f;
    for (int nn = blockIdx.x; nn < n; nn += gridDim.x)
        acc += e[nn] * ents[(size_t)nn * 128 + t];
    atomicAdd(&pooled[t], acc);
}

__global__ void k_norm(float* __restrict__ attn, float* __restrict__ pooled, int n) {
    float inv = 1.f / g_sum[0];
    for (int i = blockIdx.x * blockDim.x + threadIdx.x; i < n; i += gridDim.x * blockDim.x) {
        attn[i] *= inv;
        if (i < 128) pooled[i] *= inv;
    }
}

// ---------------- launch ----------------
extern "C" void kernel_launch(void* const* d_in, const int* in_sizes, int n_in,
                              void* d_out, int out_size) {
    const float* x     = (const float*)d_in[0];
    const int*   eidx  = (const int*)  d_in[1];
    const int*   qmask = (const int*)  d_in[3];
    const float* W1    = (const float*)d_in[5];
    const float* as1w  = (const float*)d_in[6];
    const float* ad1w  = (const float*)d_in[7];
    const float* b1    = (const float*)d_in[8];
    const float* W2    = (const float*)d_in[9];
    const float* as2w  = (const float*)d_in[10];
    const float* ad2w  = (const float*)d_in[11];
    const float* b2    = (const float*)d_in[12];
    const float* Wq    = (const float*)d_in[13];

    const int n = in_sizes[3];
    const int E = in_sizes[1] / 2;
    const int K1 = in_sizes[0] / n;
    const int ET = E + n;

    const int* src = eidx;
    const int* dst = eidx + E;

    float* out    = (float*)d_out;
    float* pooled = out;
    float* ents   = out + 128;
    float* attn   = out + 128 + (size_t)n * 128;

    void *p_deg, *p_maxu, *p_sum;
    cudaGetSymbolAddress(&p_deg,  g_deg);
    cudaGetSymbolAddress(&p_maxu, g_maxu);
    cudaGetSymbolAddress(&p_sum,  g_sum);

    cudaMemsetAsync(p_deg,  0, (size_t)n * sizeof(int));
    cudaMemsetAsync(p_maxu, 0, sizeof(unsigned));
    cudaMemsetAsync(p_sum,  0, sizeof(float));
    cudaMemsetAsync(pooled, 0, 128 * sizeof(float));

    float* g_xw1_p;  cudaGetSymbolAddress((void**)&g_xw1_p,  g_xw1);
    float* g_msg1_p; cudaGetSymbolAddress((void**)&g_msg1_p, g_msg1);

    // ---- CSR build (shared by both layers) ----
    k_hist<<<(ET + 255) / 256, 256>>>(dst, E, n);
    k_prefix<<<1, 1024>>>(n);
    k_scatter<<<(ET + 255) / 256, 256>>>(src, dst, E, n);

    // ---- layer 1 ----
    sgemm128<<<(n + 127) / 128, 256>>>(x, W1, g_xw1_p, n, K1);
    attdot1<<<(n * 4 + 255) / 256, 256>>>(as1w, ad1w, n);
    gather1<<<(n + 7) / 8, 256>>>(b1, n);

    // ---- layer 2 ----
    sgemm128<<<(n + 127) / 128, 256>>>(g_msg1_p, W2, g_xw1_p, n, 128);
    attdot2<<<(n + 7) / 8, 256>>>(as2w, ad2w, n);
    gather2<<<(n + 7) / 8, 256>>>(b2, Wq, qmask, ents, n);

    // ---- softmax + pool ----
    k_max<<<256, 256>>>(n);
    k_expsum<<<256, 256>>>(attn, n);
    k_pool<<<512, 128>>>(attn, ents, pooled, n);
    k_norm<<<(n + 255) / 256, 256>>>(attn, pooled, n);
}

// round 5
// speedup vs baseline: 2.4501x; 1.2578x over previous
#include <cuda_runtime.h>
#include <cuda_bf16.h>
#include <math.h>
#include <stdint.h>

#define NN_MAX 50000
#define E_MAX  800000

// ---------------- scratch (device globals; no allocation) ----------------
__device__ float    g_xw1 [NN_MAX * 128];
__device__ float    g_msg1[NN_MAX * 128];
__device__ float    g_as1 [NN_MAX * 4];
__device__ float    g_ad1 [NN_MAX * 4];
__device__ float    g_as2 [NN_MAX];
__device__ float    g_ad2 [NN_MAX];
__device__ float    g_logits[NN_MAX];
__device__ unsigned g_maxu[1];
__device__ float    g_sum [1];
// CSR
__device__ int      g_deg   [NN_MAX];
__device__ int      g_rowptr[NN_MAX + 1];
__device__ int      g_cursor[NN_MAX];
__device__ int      g_col   [E_MAX + NN_MAX];
// W transposed hi/lo (bf16), [N=128][K] row-major
__device__ __nv_bfloat16 g_W1tH[256 * 128];
__device__ __nv_bfloat16 g_W1tL[256 * 128];
__device__ __nv_bfloat16 g_W2tH[128 * 128];
__device__ __nv_bfloat16 g_W2tL[128 * 128];

// ---------------- helpers ----------------
__device__ __forceinline__ unsigned ford(float f) {
    unsigned u = __float_as_uint(f);
    return (u & 0x80000000u) ? ~u : (u | 0x80000000u);
}
__device__ __forceinline__ float forddec(unsigned u) {
    return (u & 0x80000000u) ? __uint_as_float(u & 0x7fffffffu) : __uint_as_float(~u);
}
__device__ __forceinline__ float lrelu(float v) { return v > 0.f ? v : 0.2f * v; }
__device__ __forceinline__ float elu(float v)   { return v > 0.f ? v : expm1f(v); }

__device__ __forceinline__ uint32_t smem_u32(const void* p) {
    uint32_t a;
    asm("{ .reg .u64 t; cvta.to.shared.u64 t, %1; cvt.u32.u64 %0, t; }" : "=r"(a) : "l"(p));
    return a;
}
__device__ __forceinline__ void ldsm4(uint32_t a, uint32_t* r) {
    asm volatile("ldmatrix.sync.aligned.m8n8.x4.shared.b16 {%0,%1,%2,%3}, [%4];"
        : "=r"(r[0]), "=r"(r[1]), "=r"(r[2]), "=r"(r[3]) : "r"(a));
}
__device__ __forceinline__ void mma16816(float* c, const uint32_t* a, uint32_t b0, uint32_t b1) {
    asm volatile(
        "mma.sync.aligned.m16n8k16.row.col.f32.bf16.bf16.f32 "
        "{%0,%1,%2,%3}, {%4,%5,%6,%7}, {%8,%9}, {%0,%1,%2,%3};"
        : "+f"(c[0]), "+f"(c[1]), "+f"(c[2]), "+f"(c[3])
        : "r"(a[0]), "r"(a[1]), "r"(a[2]), "r"(a[3]), "r"(b0), "r"(b1));
}

// ---------------- W prep: Wt_hi/lo[n*K + k] = split(W[k*128 + n]) ----------------
__global__ void k_prepW(const float* __restrict__ W, __nv_bfloat16* __restrict__ H,
                        __nv_bfloat16* __restrict__ L, int K) {
    int idx = blockIdx.x * blockDim.x + threadIdx.x;
    if (idx >= K * 128) return;
    int k = idx >> 7, nc = idx & 127;
    float v = W[idx];
    __nv_bfloat16 h = __float2bfloat16(v);
    float lo = v - __bfloat162float(h);
    H[(size_t)nc * K + k] = h;
    L[(size_t)nc * K + k] = __float2bfloat16(lo);
}

// ---------------- HMMA GEMM: C[M,128] = A[M,K] @ W[K,128], 3-term bf16 split
// fused attention dots. CTA: 128x128 tile, 8 warps of 32x64. K chunk = 64.
#define SSTR 72                      // smem row stride in bf16 elems (144B)
#define SM_AH 0
#define SM_AL 18432
#define SM_BH 36864
#define SM_BL 55296
#define SM_TOT 73728

__global__ void __launch_bounds__(256, 1)
gemm_tc(const float* __restrict__ A, int M, int K,
        const __nv_bfloat16* __restrict__ BtH, const __nv_bfloat16* __restrict__ BtL,
        float* __restrict__ C,
        const float* __restrict__ attS, const float* __restrict__ attD,
        float* __restrict__ asOut, float* __restrict__ adOut, int heads) {
    extern __shared__ __align__(128) char smem[];
    uint32_t sb = smem_u32(smem);
    int tid = threadIdx.x, lane = tid & 31, w = tid >> 5;
    int wm = w >> 1, wn = w & 1;
    int row0 = blockIdx.x * 128;
    int lr = lane & 15, lc = lane >> 4;     // ldmatrix x4 addressing

    float acc[16][4];                        // [mb*8+nb][4]
#pragma unroll
    for (int i = 0; i < 16; i++)
#pragma unroll
        for (int j = 0; j < 4; j++) acc[i][j] = 0.f;

    for (int k0 = 0; k0 < K; k0 += 64) {
        // ---- fill A hi/lo: 128 rows x 64 cols ----
#pragma unroll
        for (int i = 0; i < 8; i++) {
            int f = tid + i * 256;           // float4 slot: 128*16
            int r = f >> 4, c4 = (f & 15) << 2;
            float4 a = make_float4(0.f, 0.f, 0.f, 0.f);
            if (row0 + r < M)
                a = *(const float4*)&A[(size_t)(row0 + r) * K + k0 + c4];
            __nv_bfloat16 hx = __float2bfloat16(a.x), hy = __float2bfloat16(a.y);
            __nv_bfloat16 hz = __float2bfloat16(a.z), hw = __float2bfloat16(a.w);
            __nv_bfloat162 h01, h23, l01, l23;
            h01.x = hx; h01.y = hy; h23.x = hz; h23.y = hw;
            l01.x = __float2bfloat16(a.x - __bfloat162float(hx));
            l01.y = __float2bfloat16(a.y - __bfloat162float(hy));
            l23.x = __float2bfloat16(a.z - __bfloat162float(hz));
            l23.y = __float2bfloat16(a.w - __bfloat162float(hw));
            uint32_t off = (uint32_t)(r * SSTR + c4) * 2;
            *(__nv_bfloat162*)(smem + SM_AH + off)     = h01;
            *(__nv_bfloat162*)(smem + SM_AH + off + 4) = h23;
            *(__nv_bfloat162*)(smem + SM_AL + off)     = l01;
            *(__nv_bfloat162*)(smem + SM_AL + off + 4) = l23;
        }
        // ---- fill B hi/lo: 128 n-rows x 64 k-cols (from Bt[n][k]) ----
#pragma unroll
        for (int i = 0; i < 4; i++) {
            int f = tid + i * 256;           // uint4 slot: 128*8
            int r = f >> 3, u = (f & 7) << 3;
            uint32_t off = (uint32_t)(r * SSTR + u) * 2;
            *(uint4*)(smem + SM_BH + off) = *(const uint4*)&BtH[(size_t)r * K + k0 + u];
            *(uint4*)(smem + SM_BL + off) = *(const uint4*)&BtL[(size_t)r * K + k0 + u];
        }
        __syncthreads();

#pragma unroll
        for (int ks = 0; ks < 4; ks++) {
            uint32_t aH[2][4], aL[2][4];
#pragma unroll
            for (int mb = 0; mb < 2; mb++) {
                uint32_t off = (uint32_t)((wm * 32 + mb * 16 + lr) * SSTR + ks * 16 + lc * 8) * 2;
                ldsm4(sb + SM_AH + off, aH[mb]);
                ldsm4(sb + SM_AL + off, aL[mb]);
            }
#pragma unroll
            for (int nbp = 0; nbp < 4; nbp++) {
                uint32_t offB = (uint32_t)((wn * 64 + nbp * 16 + lr) * SSTR + ks * 16 + lc * 8) * 2;
                uint32_t bh[4], bl[4];
                ldsm4(sb + SM_BH + offB, bh);
                ldsm4(sb + SM_BL + offB, bl);
#pragma unroll
                for (int mb = 0; mb < 2; mb++) {
                    float* c0 = acc[mb * 8 + nbp * 2];
                    float* c1 = acc[mb * 8 + nbp * 2 + 1];
                    mma16816(c0, aH[mb], bh[0], bh[2]);
                    mma16816(c0, aL[mb], bh[0], bh[2]);
                    mma16816(c0, aH[mb], bl[0], bl[2]);
                    mma16816(c1, aH[mb], bh[1], bh[3]);
                    mma16816(c1, aL[mb], bh[1], bh[3]);
                    mma16816(c1, aH[mb], bl[1], bl[3]);
                }
            }
        }
        __syncthreads();
    }

    // ---- epilogue: store C + fused attention dots ----
    int g = lane >> 2, tq = lane & 3;
    float pS[8], pD[8];                      // [mb*4 + half*2 + sub]
#pragma unroll
    for (int i = 0; i < 8; i++) { pS[i] = 0.f; pD[i] = 0.f; }

#pragma unroll
    for (int mb = 0; mb < 2; mb++) {
#pragma unroll
        for (int nb = 0; nb < 8; nb++) {
            int col = wn * 64 + nb * 8 + tq * 2;
            float* c = acc[mb * 8 + nb];
            float s0 = attS[col], s1 = attS[col + 1];
            float d0 = attD[col], d1 = attD[col + 1];
            int sub = nb >> 2;
            pS[mb * 4 + sub]     += c[0] * s0 + c[1] * s1;
            pS[mb * 4 + 2 + sub] += c[2] * s0 + c[3] * s1;
            pD[mb * 4 + sub]     += c[0] * d0 + c[1] * d1;
            pD[mb * 4 + 2 + sub] += c[2] * d0 + c[3] * d1;
            int r = row0 + wm * 32 + mb * 16 + g;
            if (r < M)     *(float2*)&C[(size_t)r * 128 + col]       = make_float2(c[0], c[1]);
            if (r + 8 < M) *(float2*)&C[(size_t)(r + 8) * 128 + col] = make_float2(c[2], c[3]);
        }
    }
#pragma unroll
    for (int o = 1; o <= 2; o <<= 1) {
#pragma unroll
        for (int i = 0; i < 8; i++) {
            pS[i] += __shfl_xor_sync(0xffffffffu, pS[i], o);
            pD[i] += __shfl_xor_sync(0xffffffffu, pD[i], o);
        }
    }
    if (tq == 0) {
#pragma unroll
        for (int mb = 0; mb < 2; mb++) {
#pragma unroll
            for (int half = 0; half < 2; half++) {
                int r = row0 + wm * 32 + mb * 16 + g + half * 8;
                if (r < M) {
                    int i0 = mb * 4 + half * 2;
                    if (heads == 4) {
                        asOut[r * 4 + wn * 2 + 0] = pS[i0 + 0];
                        asOut[r * 4 + wn * 2 + 1] = pS[i0 + 1];
                        adOut[r * 4 + wn * 2 + 0] = pD[i0 + 0];
                        adOut[r * 4 + wn * 2 + 1] = pD[i0 + 1];
                    } else {
                        atomicAdd(&asOut[r], pS[i0] + pS[i0 + 1]);
                        atomicAdd(&adOut[r], pD[i0] + pD[i0 + 1]);
                    }
                }
            }
        }
    }
}

// ---------------- CSR build ----------------
__global__ void k_hist(const int* __restrict__ dst, int E, int n) {
    int e = blockIdx.x * blockDim.x + threadIdx.x;
    if (e >= E + n) return;
    int d = (e < E) ? dst[e] : (e - E);
    atomicAdd(&g_deg[d], 1);
}

__global__ void k_prefix(int n) {
    __shared__ int sh[1024];
    int t = threadIdx.x;
    int chunk = (n + 1023) / 1024;
    int lo = t * chunk, hi = min(lo + chunk, n);
    int part = 0;
    for (int i = lo; i < hi; i++) part += g_deg[i];
    sh[t] = part;
    __syncthreads();
    for (int off = 1; off < 1024; off <<= 1) {
        int v = (t >= off) ? sh[t - off] : 0;
        __syncthreads();
        sh[t] += v;
        __syncthreads();
    }
    int base = (t == 0) ? 0 : sh[t - 1];
    for (int i = lo; i < hi; i++) {
        g_rowptr[i] = base;
        g_cursor[i] = base;
        base += g_deg[i];
    }
    if (t == 0) g_rowptr[n] = sh[1023];
}

__global__ void k_scatter(const int* __restrict__ src, const int* __restrict__ dst, int E, int n) {
    int e = blockIdx.x * blockDim.x + threadIdx.x;
    if (e >= E + n) return;
    int s, d;
    if (e < E) { s = src[e]; d = dst[e]; } else { s = e - E; d = s; }
    int pos = atomicAdd(&g_cursor[d], 1);
    g_col[pos] = s;
}

// ---------------- layer-1 gather ----------------
__global__ void gather1(const float* __restrict__ b1, int n) {
    int d = (blockIdx.x * blockDim.x + threadIdx.x) >> 5;
    int lane = threadIdx.x & 31;
    if (d >= n) return;
    int r0 = g_rowptr[d], r1 = g_rowptr[d + 1];
    float4 ad = *(const float4*)&g_ad1[d * 4];

    float4 mx = make_float4(-3.4e38f, -3.4e38f, -3.4e38f, -3.4e38f);
    for (int e = r0 + lane; e < r1; e += 32) {
        int s = g_col[e];
        float4 as = *(const float4*)&g_as1[s * 4];
        mx.x = fmaxf(mx.x, lrelu(as.x + ad.x));
        mx.y = fmaxf(mx.y, lrelu(as.y + ad.y));
        mx.z = fmaxf(mx.z, lrelu(as.z + ad.z));
        mx.w = fmaxf(mx.w, lrelu(as.w + ad.w));
    }
#pragma unroll
    for (int o = 16; o; o >>= 1) {
        mx.x = fmaxf(mx.x, __shfl_xor_sync(0xffffffffu, mx.x, o));
        mx.y = fmaxf(mx.y, __shfl_xor_sync(0xffffffffu, mx.y, o));
        mx.z = fmaxf(mx.z, __shfl_xor_sync(0xffffffffu, mx.z, o));
        mx.w = fmaxf(mx.w, __shfl_xor_sync(0xffffffffu, mx.w, o));
    }

    int h = lane >> 3;
    float m_h  = (h == 0) ? mx.x : (h == 1) ? mx.y : (h == 2) ? mx.z : mx.w;
    float ad_h = (h == 0) ? ad.x : (h == 1) ? ad.y : (h == 2) ? ad.z : ad.w;

    float4 acc = make_float4(0.f, 0.f, 0.f, 0.f);
    float den = 0.f;
    int e = r0;
    for (; e + 1 < r1; e += 2) {
        int s0 = g_col[e], s1 = g_col[e + 1];
        float w0 = __expf(lrelu(g_as1[s0 * 4 + h] + ad_h) - m_h);
        float w1 = __expf(lrelu(g_as1[s1 * 4 + h] + ad_h) - m_h);
        float4 x0 = *(const float4*)&g_xw1[s0 * 128 + lane * 4];
        float4 x1 = *(const float4*)&g_xw1[s1 * 128 + lane * 4];
        den += w0 + w1;
        acc.x += w0 * x0.x + w1 * x1.x;
        acc.y += w0 * x0.y + w1 * x1.y;
        acc.z += w0 * x0.z + w1 * x1.z;
        acc.w += w0 * x0.w + w1 * x1.w;
    }
    if (e < r1) {
        int s0 = g_col[e];
        float w0 = __expf(lrelu(g_as1[s0 * 4 + h] + ad_h) - m_h);
        float4 x0 = *(const float4*)&g_xw1[s0 * 128 + lane * 4];
        den += w0;
        acc.x += w0 * x0.x; acc.y += w0 * x0.y;
        acc.z += w0 * x0.z; acc.w += w0 * x0.w;
    }
    float inv = 1.f / (den + 1e-16f);
    float4 b = *(const float4*)&b1[lane * 4];
    float4 v;
    v.x = elu(acc.x * inv + b.x);
    v.y = elu(acc.y * inv + b.y);
    v.z = elu(acc.z * inv + b.z);
    v.w = elu(acc.w * inv + b.w);
    *(float4*)&g_msg1[d * 128 + lane * 4] = v;
}

// ---------------- layer-2 gather: fused ents + logits ----------------
__global__ void gather2(const float* __restrict__ b2, const float* __restrict__ Wq,
                        const int* __restrict__ qmask, float* __restrict__ ents, int n) {
    int d = (blockIdx.x * blockDim.x + threadIdx.x) >> 5;
    int lane = threadIdx.x & 31;
    if (d >= n) return;
    int r0 = g_rowptr[d], r1 = g_rowptr[d + 1];
    float ad = g_ad2[d];

    float mx = -3.4e38f;
    for (int e = r0 + lane; e < r1; e += 32)
        mx = fmaxf(mx, lrelu(g_as2[g_col[e]] + ad));
#pragma unroll
    for (int o = 16; o; o >>= 1) mx = fmaxf(mx, __shfl_xor_sync(0xffffffffu, mx, o));

    float4 acc = make_float4(0.f, 0.f, 0.f, 0.f);
    float den = 0.f;
    int e = r0;
    for (; e + 1 < r1; e += 2) {
        int s0 = g_col[e], s1 = g_col[e + 1];
        float w0 = __expf(lrelu(g_as2[s0] + ad) - mx);
        float w1 = __expf(lrelu(g_as2[s1] + ad) - mx);
        float4 x0 = *(const float4*)&g_xw1[s0 * 128 + lane * 4];
        float4 x1 = *(const float4*)&g_xw1[s1 * 128 + lane * 4];
        den += w0 + w1;
        acc.x += w0 * x0.x + w1 * x1.x;
        acc.y += w0 * x0.y + w1 * x1.y;
        acc.z += w0 * x0.z + w1 * x1.z;
        acc.w += w0 * x0.w + w1 * x1.w;
    }
    if (e < r1) {
        int s0 = g_col[e];
        float w0 = __expf(lrelu(g_as2[s0] + ad) - mx);
        float4 x0 = *(const float4*)&g_xw1[s0 * 128 + lane * 4];
        den += w0;
        acc.x += w0 * x0.x; acc.y += w0 * x0.y;
        acc.z += w0 * x0.z; acc.w += w0 * x0.w;
    }
    float inv = 1.f / (den + 1e-16f);
    float4 b = *(const float4*)&b2[lane * 4];
    float4 v;
    v.x = elu(acc.x * inv + b.x);
    v.y = elu(acc.y * inv + b.y);
    v.z = elu(acc.z * inv + b.z);
    v.w = elu(acc.w * inv + b.w);
    *(float4*)&ents[(size_t)d * 128 + lane * 4] = v;

    float4 wq = *(const float4*)&Wq[lane * 4];
    float dotp = v.x * wq.x + v.y * wq.y + v.z * wq.z + v.w * wq.w;
#pragma unroll
    for (int o = 16; o; o >>= 1) dotp += __shfl_xor_sync(0xffffffffu, dotp, o);
    if (lane == 0)
        g_logits[d] = dotp + ((float)qmask[d] - 1.f) * 1e9f;
}

// ---------------- softmax + pooling ----------------
__global__ void k_max(int n) {
    float m = -3.4e38f;
    for (int i = blockIdx.x * blockDim.x + threadIdx.x; i < n; i += gridDim.x * blockDim.x)
        m = fmaxf(m, g_logits[i]);
#pragma unroll
    for (int o = 16; o; o >>= 1) m = fmaxf(m, __shfl_xor_sync(0xffffffffu, m, o));
    if ((threadIdx.x & 31) == 0) atomicMax(&g_maxu[0], ford(m));
}

__global__ void k_expsum(float* __restrict__ e_out, int n) {
    float M = forddec(g_maxu[0]);
    float s = 0.f;
    for (int i = blockIdx.x * blockDim.x + threadIdx.x; i < n; i += gridDim.x * blockDim.x) {
        float e = __expf(g_logits[i] - M);
        e_out[i] = e;
        s += e;
    }
#pragma unroll
    for (int o = 16; o; o >>= 1) s += __shfl_xor_sync(0xffffffffu, s, o);
    if ((threadIdx.x & 31) == 0) atomicAdd(&g_sum[0], s);
}

__global__ void k_pool(const float* __restrict__ e, const float* __restrict__ ents,
                       float* __restrict__ pooled, int n) {
    int t = threadIdx.x;  // 128 = channel
    float acc = 0.f;
    for (int nn = blockIdx.x; nn < n; nn += gridDim.x)
        acc += e[nn] * ents[(size_t)nn * 128 + t];
    atomicAdd(&pooled[t], acc);
}

__global__ void k_norm(float* __restrict__ attn, float* __restrict__ pooled, int n) {
    float inv = 1.f / g_sum[0];
    for (int i = blockIdx.x * blockDim.x + threadIdx.x; i < n; i += gridDim.x * blockDim.x) {
        attn[i] *= inv;
        if (i < 128) pooled[i] *= inv;
    }
}

// ---------------- launch ----------------
extern "C" void kernel_launch(void* const* d_in, const int* in_sizes, int n_in,
                              void* d_out, int out_size) {
    const float* x     = (const float*)d_in[0];
    const int*   eidx  = (const int*)  d_in[1];
    const int*   qmask = (const int*)  d_in[3];
    const float* W1    = (const float*)d_in[5];
    const float* as1w  = (const float*)d_in[6];
    const float* ad1w  = (const float*)d_in[7];
    const float* b1    = (const float*)d_in[8];
    const float* W2    = (const float*)d_in[9];
    const float* as2w  = (const float*)d_in[10];
    const float* ad2w  = (const float*)d_in[11];
    const float* b2    = (const float*)d_in[12];
    const float* Wq    = (const float*)d_in[13];

    const int n = in_sizes[3];
    const int E = in_sizes[1] / 2;
    const int K1 = in_sizes[0] / n;
    const int ET = E + n;

    const int* src = eidx;
    const int* dst = eidx + E;

    float* out    = (float*)d_out;
    float* pooled = out;
    float* ents   = out + 128;
    float* attn   = out + 128 + (size_t)n * 128;

    void *p_deg, *p_maxu, *p_sum, *p_as2, *p_ad2;
    cudaGetSymbolAddress(&p_deg,  g_deg);
    cudaGetSymbolAddress(&p_maxu, g_maxu);
    cudaGetSymbolAddress(&p_sum,  g_sum);
    cudaGetSymbolAddress(&p_as2,  g_as2);
    cudaGetSymbolAddress(&p_ad2,  g_ad2);

    cudaMemsetAsync(p_deg,  0, (size_t)n * sizeof(int));
    cudaMemsetAsync(p_maxu, 0, sizeof(unsigned));
    cudaMemsetAsync(p_sum,  0, sizeof(float));
    cudaMemsetAsync(pooled, 0, 128 * sizeof(float));
    cudaMemsetAsync(p_as2,  0, (size_t)n * sizeof(float));
    cudaMemsetAsync(p_ad2,  0, (size_t)n * sizeof(float));

    float *g_xw1_p, *g_msg1_p, *g_as1_p, *g_ad1_p, *g_as2_p, *g_ad2_p;
    cudaGetSymbolAddress((void**)&g_xw1_p,  g_xw1);
    cudaGetSymbolAddress((void**)&g_msg1_p, g_msg1);
    cudaGetSymbolAddress((void**)&g_as1_p,  g_as1);
    cudaGetSymbolAddress((void**)&g_ad1_p,  g_ad1);
    cudaGetSymbolAddress((void**)&g_as2_p,  g_as2);
    cudaGetSymbolAddress((void**)&g_ad2_p,  g_ad2);
    __nv_bfloat16 *w1h, *w1l, *w2h, *w2l;
    cudaGetSymbolAddress((void**)&w1h, g_W1tH);
    cudaGetSymbolAddress((void**)&w1l, g_W1tL);
    cudaGetSymbolAddress((void**)&w2h, g_W2tH);
    cudaGetSymbolAddress((void**)&w2l, g_W2tL);

    cudaFuncSetAttribute(gemm_tc, cudaFuncAttributeMaxDynamicSharedMemorySize, SM_TOT);

    const int gblk = (n + 127) / 128;

    // ---- CSR build + W prep ----
    k_hist<<<(ET + 255) / 256, 256>>>(dst, E, n);
    k_prefix<<<1, 1024>>>(n);
    k_scatter<<<(ET + 255) / 256, 256>>>(src, dst, E, n);
    k_prepW<<<(K1 * 128 + 255) / 256, 256>>>(W1, w1h, w1l, K1);
    k_prepW<<<(128 * 128 + 255) / 256, 256>>>(W2, w2h, w2l, 128);

    // ---- layer 1 ----
    gemm_tc<<<gblk, 256, SM_TOT>>>(x, n, K1, w1h, w1l, g_xw1_p,
                                   as1w, ad1w, g_as1_p, g_ad1_p, 4);
    gather1<<<(n + 7) / 8, 256>>>(b1, n);

    // ---- layer 2 ----
    gemm_tc<<<gblk, 256, SM_TOT>>>(g_msg1_p, n, 128, w2h, w2l, g_xw1_p,
                                   as2w, ad2w, g_as2_p, g_ad2_p, 1);
    gather2<<<(n + 7) / 8, 256>>>(b2, Wq, qmask, ents, n);

    // ---- softmax + pool ----
    k_max<<<256, 256>>>(n);
    k_expsum<<<256, 256>>>(attn, n);
    k_pool<<<512, 128>>>(attn, ents, pooled, n);
    k_norm<<<(n + 255) / 256, 256>>>(attn, pooled, n);
}